// round 6
// baseline (speedup 1.0000x reference)
#include <cuda_runtime.h>

// ---------------------------------------------------------------------------
// GraphRNNDecoder rollout. N=4096 rows, T=128 steps, D=4, H=256.
// 128 persistent CTAs x 1024 threads, 32 rows per CTA.
// R5: warp covers ALL 32 rows. Lane (rg in [0,8), u in [0,4)) handles
// 8 gate-units (2 j2 x 4 gates) x 4 rows. Weight LDG.128 = 64B unique x8 dup
// -> 1 wavefront (vs 4); h LDS = 128B unique -> L1 wavefronts halved.
// ---------------------------------------------------------------------------

#define T_STEPS 128
#define DIN     4
#define HID     256
#define G4      1024
#define MROWS   32
#define NCTA    128
#define KC      64

// k-chunk packed weights [kc][unit] -> float4 of W[unit][4kc..4kc+3]
__device__ float4 g_whh[KC * G4];   // 1 MB
__device__ float4 g_fc1[KC * HID];  // 256 KB
__device__ float4 g_fc2[KC * HID];  // 256 KB

__global__ void pack_kernel(const float* __restrict__ W_hh,
                            const float* __restrict__ fc1_w,
                            const float* __restrict__ fc2_w) {
    int i = blockIdx.x * blockDim.x + threadIdx.x;
    if (i < KC * G4) {
        int kc = i >> 10, j = i & 1023;
        g_whh[i] = *reinterpret_cast<const float4*>(W_hh + j * HID + kc * 4);
    }
    if (i < KC * HID) {
        int kc = i >> 8, j = i & 255;
        g_fc1[i] = *reinterpret_cast<const float4*>(fc1_w + j * HID + kc * 4);
        g_fc2[i] = *reinterpret_cast<const float4*>(fc2_w + j * HID + kc * 4);
    }
}

// ---- packed f32x2 helpers --------------------------------------------------
__device__ __forceinline__ unsigned long long pk2(float lo, float hi) {
    unsigned long long r;
    asm("mov.b64 %0, {%1, %2};" : "=l"(r) : "f"(lo), "f"(hi));
    return r;
}
__device__ __forceinline__ void fma2(unsigned long long& d,
                                     unsigned long long a,
                                     unsigned long long b) {
    asm("fma.rn.f32x2 %0, %1, %2, %0;" : "+l"(d) : "l"(a), "l"(b));
}
__device__ __forceinline__ void unpk2(unsigned long long v, float& lo, float& hi) {
    asm("mov.b64 {%0, %1}, %2;" : "=f"(lo), "=f"(hi) : "l"(v));
}
__device__ __forceinline__ float sigf(float x) {
    return __fdividef(1.0f, 1.0f + __expf(-x));
}
__device__ __forceinline__ float tanhf_fast(float x) {
    float e = __expf(2.0f * x);
    return 1.0f - __fdividef(2.0f, e + 1.0f);
}

// ---- shared layout (float offsets) -----------------------------------------
#define SBUF      9216          // one [256][36] activation buffer
#define OFF_BUF   0             // 3 buffers: h ping, h pong, p2
#define OFF_C     27648         // [256][36] c state
#define OFF_PREV  36864         // [32][4]
#define OFF_WIH   36992         // [1024][4]
#define OFF_BG    41088         // [1024]
#define OFF_FB1   42112         // [256]
#define OFF_FB2   42368         // [256]
#define OFF_FC3   42624         // [256][4]  fc3T[k][d]
#define OFF_B3    43648         // [4]
#define SMEM_FLOATS 43652
#define SMEM_BYTES  (SMEM_FLOATS * 4)

// fc: 2 units (jb, jb+4) x 4 rows (r0..r0+3), relu, dst [unit][36]
__device__ __forceinline__ void fc_phase(const float* __restrict__ src,
                                         float* __restrict__ dst,
                                         const float4* __restrict__ wbase,
                                         const float* __restrict__ bsh,
                                         int jb, int r0) {
    unsigned long long acc[4];
    {
        float b0 = bsh[jb], b1 = bsh[jb + 4];
        acc[0] = acc[1] = pk2(b0, b0);
        acc[2] = acc[3] = pk2(b1, b1);
    }
    const float* hq = src + r0;
    const float4* gw = wbase + jb;
#pragma unroll 2
    for (int kc = 0; kc < KC; kc++) {
        const float* hb = hq + kc * 144;
        ulonglong2 h0 = *reinterpret_cast<const ulonglong2*>(hb);
        ulonglong2 h1 = *reinterpret_cast<const ulonglong2*>(hb + 36);
        ulonglong2 h2 = *reinterpret_cast<const ulonglong2*>(hb + 72);
        ulonglong2 h3 = *reinterpret_cast<const ulonglong2*>(hb + 108);
        const float4* wk = gw + kc * HID;
#pragma unroll
        for (int half = 0; half < 2; half++) {
            float4 wv = wk[half * 4];
            const int a = half * 2;
            unsigned long long w2;
            w2 = pk2(wv.x, wv.x); fma2(acc[a], w2, h0.x); fma2(acc[a + 1], w2, h0.y);
            w2 = pk2(wv.y, wv.y); fma2(acc[a], w2, h1.x); fma2(acc[a + 1], w2, h1.y);
            w2 = pk2(wv.z, wv.z); fma2(acc[a], w2, h2.x); fma2(acc[a + 1], w2, h2.y);
            w2 = pk2(wv.w, wv.w); fma2(acc[a], w2, h3.x); fma2(acc[a + 1], w2, h3.y);
        }
    }
#pragma unroll
    for (int half = 0; half < 2; half++) {
        const int j = jb + half * 4;
        float v0, v1, v2, v3;
        unpk2(acc[half * 2], v0, v1);
        unpk2(acc[half * 2 + 1], v2, v3);
        *reinterpret_cast<float4*>(dst + j * 36 + r0) =
            make_float4(fmaxf(v0, 0.f), fmaxf(v1, 0.f), fmaxf(v2, 0.f), fmaxf(v3, 0.f));
    }
}

__global__ void __launch_bounds__(1024, 1)
rnn_rollout_kernel(const float* __restrict__ inputs,
                   const float* __restrict__ W_ih,
                   const float* __restrict__ b_ih,
                   const float* __restrict__ b_hh,
                   const float* __restrict__ fc1_b,
                   const float* __restrict__ fc2_b,
                   const float* __restrict__ fc3_w,
                   const float* __restrict__ fc3_b,
                   float* __restrict__ out) {
    extern __shared__ float sm[];
    float* buf    = sm + OFF_BUF;
    float* csh    = sm + OFF_C;
    float* prevsh = sm + OFF_PREV;
    float* wihsh  = sm + OFF_WIH;
    float* bgsh   = sm + OFF_BG;
    float* fb1sh  = sm + OFF_FB1;
    float* fb2sh  = sm + OFF_FB2;
    float* fc3T   = sm + OFF_FC3;
    float* b3sh   = sm + OFF_B3;

    const int tid  = threadIdx.x;
    const int w    = tid >> 5;       // warp 0..31
    const int l    = tid & 31;
    const int u    = l & 3;          // unit lane
    const int rg   = l >> 2;         // rowgroup 0..7
    const int r0   = rg * 4;         // 4 rows per thread
    const int jb   = w * 8 + u;      // thread's j2 pair: jb, jb+4
    const int row0 = blockIdx.x * MROWS;

    // ---- one-time init ----
    *reinterpret_cast<float4*>(wihsh + tid * 4) =
        *reinterpret_cast<const float4*>(W_ih + tid * 4);
    bgsh[tid] = b_ih[tid] + b_hh[tid];
    if (tid < HID) { fb1sh[tid] = fc1_b[tid]; fb2sh[tid] = fc2_b[tid]; }
    fc3T[tid] = fc3_w[(tid & 3) * HID + (tid >> 2)];
    if (tid < DIN) b3sh[tid] = fc3_b[tid];
    for (int i = tid; i < 3 * SBUF; i += 1024) buf[i] = 0.0f;
    for (int i = tid; i < SBUF; i += 1024) csh[i] = 0.0f;
    if (tid < MROWS * DIN)
        prevsh[tid] = inputs[((size_t)(row0 + (tid >> 2)) * T_STEPS) * DIN + (tid & 3)];
    __syncthreads();

    for (int t = 0; t < T_STEPS; t++) {
        const int par = t & 1;
        float* hin  = buf + par * SBUF;
        float* hout = buf + (par ^ 1) * SBUF;
        float* p1   = hin;                 // fc1 overwrites dead h_in
        float* p2   = buf + 2 * SBUF;

        // ---- phase A: gate GEMM (8 units x 4 rows per thread) ----
        unsigned long long acc[16];
        {
            float4 pv0 = *reinterpret_cast<const float4*>(prevsh + r0 * 4);
            float4 pv1 = *reinterpret_cast<const float4*>(prevsh + (r0 + 1) * 4);
            float4 pv2 = *reinterpret_cast<const float4*>(prevsh + (r0 + 2) * 4);
            float4 pv3 = *reinterpret_cast<const float4*>(prevsh + (r0 + 3) * 4);
#pragma unroll
            for (int half = 0; half < 2; half++) {
                const int j2 = jb + half * 4;
#pragma unroll
                for (int g = 0; g < 4; g++) {
                    const int unit = g * 256 + j2;
                    float4 wg = *reinterpret_cast<const float4*>(wihsh + unit * 4);
                    float b = bgsh[unit];
                    float s0 = b + wg.x*pv0.x + wg.y*pv0.y + wg.z*pv0.z + wg.w*pv0.w;
                    float s1 = b + wg.x*pv1.x + wg.y*pv1.y + wg.z*pv1.z + wg.w*pv1.w;
                    float s2 = b + wg.x*pv2.x + wg.y*pv2.y + wg.z*pv2.z + wg.w*pv2.w;
                    float s3 = b + wg.x*pv3.x + wg.y*pv3.y + wg.z*pv3.z + wg.w*pv3.w;
                    acc[(half * 4 + g) * 2]     = pk2(s0, s1);
                    acc[(half * 4 + g) * 2 + 1] = pk2(s2, s3);
                }
            }
        }
        {
            const float* hq = hin + r0;
            const float4* gw = g_whh + jb;
#pragma unroll 1
            for (int kc = 0; kc < KC; kc++) {
                const float* hb = hq + kc * 144;
                ulonglong2 h0 = *reinterpret_cast<const ulonglong2*>(hb);
                ulonglong2 h1 = *reinterpret_cast<const ulonglong2*>(hb + 36);
                ulonglong2 h2 = *reinterpret_cast<const ulonglong2*>(hb + 72);
                ulonglong2 h3 = *reinterpret_cast<const ulonglong2*>(hb + 108);
                const float4* wk = gw + kc * G4;
#pragma unroll
                for (int half = 0; half < 2; half++) {
#pragma unroll
                    for (int g = 0; g < 4; g++) {
                        float4 wv = wk[g * 256 + half * 4];
                        const int a = (half * 4 + g) * 2;
                        unsigned long long w2;
                        w2 = pk2(wv.x, wv.x); fma2(acc[a], w2, h0.x); fma2(acc[a+1], w2, h0.y);
                        w2 = pk2(wv.y, wv.y); fma2(acc[a], w2, h1.x); fma2(acc[a+1], w2, h1.y);
                        w2 = pk2(wv.z, wv.z); fma2(acc[a], w2, h2.x); fma2(acc[a+1], w2, h2.y);
                        w2 = pk2(wv.w, wv.w); fma2(acc[a], w2, h3.x); fma2(acc[a+1], w2, h3.y);
                    }
                }
            }
        }
        // ---- fused LSTM elementwise: 2 j2 x 4 rows per thread ----
#pragma unroll
        for (int half = 0; half < 2; half++) {
            const int j2 = jb + half * 4;
            const int a  = half * 8;
            float4 cv = *reinterpret_cast<const float4*>(csh + j2 * 36 + r0);
            float i0,i1,i2,i3, f0,f1,f2,f3, g0,g1,g2,g3, o0,o1,o2,o3;
            unpk2(acc[a + 0], i0, i1); unpk2(acc[a + 1], i2, i3);
            unpk2(acc[a + 2], f0, f1); unpk2(acc[a + 3], f2, f3);
            unpk2(acc[a + 4], g0, g1); unpk2(acc[a + 5], g2, g3);
            unpk2(acc[a + 6], o0, o1); unpk2(acc[a + 7], o2, o3);
            float c0 = sigf(f0) * cv.x + sigf(i0) * tanhf_fast(g0);
            float c1 = sigf(f1) * cv.y + sigf(i1) * tanhf_fast(g1);
            float c2 = sigf(f2) * cv.z + sigf(i2) * tanhf_fast(g2);
            float c3 = sigf(f3) * cv.w + sigf(i3) * tanhf_fast(g3);
            *reinterpret_cast<float4*>(csh + j2 * 36 + r0) = make_float4(c0, c1, c2, c3);
            *reinterpret_cast<float4*>(hout + j2 * 36 + r0) =
                make_float4(sigf(o0) * tanhf_fast(c0), sigf(o1) * tanhf_fast(c1),
                            sigf(o2) * tanhf_fast(c2), sigf(o3) * tanhf_fast(c3));
        }
        __syncthreads();

        // ---- fc1: hout -> p1 ----
        fc_phase(hout, p1, g_fc1, fb1sh, jb, r0);
        __syncthreads();

        // ---- fc2: p1 -> p2 ----
        fc_phase(p1, p2, g_fc2, fb2sh, jb, r0);
        __syncthreads();

        // ---- fc3 + residual: warp w = row w; lane = (s in [0,8)) * 4 + d ----
        {
            const int row = w;
            const int d   = l & 3;
            const int s   = l >> 2;
            const float* pp = p2 + row;
            float a0 = 0.f;
#pragma unroll 8
            for (int i = 0; i < 32; i++) {
                const int k = i * 8 + s;
                a0 = fmaf(pp[k * 36], fc3T[k * 4 + d], a0);
            }
            a0 += __shfl_xor_sync(0xffffffffu, a0, 4);
            a0 += __shfl_xor_sync(0xffffffffu, a0, 8);
            a0 += __shfl_xor_sync(0xffffffffu, a0, 16);
            if (s == 0) {
                float r = a0 + b3sh[d] + prevsh[row * 4 + d];
                out[((size_t)(row0 + row) * T_STEPS + t) * DIN + d] = r;
                prevsh[row * 4 + d] = r;
            }
        }
        __syncthreads();
    }
}

extern "C" void kernel_launch(void* const* d_in, const int* in_sizes, int n_in,
                              void* d_out, int out_size) {
    const float* inputs = (const float*)d_in[0];
    const float* W_ih   = (const float*)d_in[1];
    const float* W_hh   = (const float*)d_in[2];
    const float* b_ih   = (const float*)d_in[3];
    const float* b_hh   = (const float*)d_in[4];
    const float* fc1_w  = (const float*)d_in[5];
    const float* fc1_b  = (const float*)d_in[6];
    const float* fc2_w  = (const float*)d_in[7];
    const float* fc2_b  = (const float*)d_in[8];
    const float* fc3_w  = (const float*)d_in[9];
    const float* fc3_b  = (const float*)d_in[10];
    float* out = (float*)d_out;

    pack_kernel<<<64, 1024>>>(W_hh, fc1_w, fc2_w);

    cudaFuncSetAttribute(rnn_rollout_kernel,
                         cudaFuncAttributeMaxDynamicSharedMemorySize, SMEM_BYTES);
    rnn_rollout_kernel<<<NCTA, 1024, SMEM_BYTES>>>(
        inputs, W_ih, b_ih, b_hh, fc1_b, fc2_b, fc3_w, fc3_b, out);
}

// round 7
// speedup vs baseline: 1.0598x; 1.0598x over previous
#include <cuda_runtime.h>

// ---------------------------------------------------------------------------
// GraphRNNDecoder rollout. N=4096 rows, T=128 steps, D=4, H=256.
// 128 persistent CTAs x 1024 threads, 32 rows per CTA.
// R6: lane = output unit (coalesced weight LDG, 512B/instr), h via
// FULL-BROADCAST LDS (all 32 lanes same address ~= 1 wavefront).
// Phase A: thread = 1 j2 x 4 gates x 8 rows -> 26 wf per 32 FMA-cyc (FMA-bound).
// fc1/fc2: thread = 2 units x 8 rows on 16 warps.
// ---------------------------------------------------------------------------

#define T_STEPS 128
#define DIN     4
#define HID     256
#define G4      1024
#define MROWS   32
#define NCTA    128
#define KC      64

// k-chunk packed weights [kc][unit] -> float4 of W[unit][4kc..4kc+3]
__device__ float4 g_whh[KC * G4];   // 1 MB
__device__ float4 g_fc1[KC * HID];  // 256 KB
__device__ float4 g_fc2[KC * HID];  // 256 KB

__global__ void pack_kernel(const float* __restrict__ W_hh,
                            const float* __restrict__ fc1_w,
                            const float* __restrict__ fc2_w) {
    int i = blockIdx.x * blockDim.x + threadIdx.x;
    if (i < KC * G4) {
        int kc = i >> 10, j = i & 1023;
        g_whh[i] = *reinterpret_cast<const float4*>(W_hh + j * HID + kc * 4);
    }
    if (i < KC * HID) {
        int kc = i >> 8, j = i & 255;
        g_fc1[i] = *reinterpret_cast<const float4*>(fc1_w + j * HID + kc * 4);
        g_fc2[i] = *reinterpret_cast<const float4*>(fc2_w + j * HID + kc * 4);
    }
}

// ---- packed f32x2 helpers --------------------------------------------------
__device__ __forceinline__ unsigned long long pk2(float lo, float hi) {
    unsigned long long r;
    asm("mov.b64 %0, {%1, %2};" : "=l"(r) : "f"(lo), "f"(hi));
    return r;
}
__device__ __forceinline__ void fma2(unsigned long long& d,
                                     unsigned long long a,
                                     unsigned long long b) {
    asm("fma.rn.f32x2 %0, %1, %2, %0;" : "+l"(d) : "l"(a), "l"(b));
}
__device__ __forceinline__ void unpk2(unsigned long long v, float& lo, float& hi) {
    asm("mov.b64 {%0, %1}, %2;" : "=f"(lo), "=f"(hi) : "l"(v));
}
__device__ __forceinline__ float sigf(float x) {
    return __fdividef(1.0f, 1.0f + __expf(-x));
}
__device__ __forceinline__ float tanhf_fast(float x) {
    float e = __expf(2.0f * x);
    return 1.0f - __fdividef(2.0f, e + 1.0f);
}

// ---- shared layout (float offsets) -----------------------------------------
#define SBUF      9216          // one [256][36] activation buffer
#define OFF_BUF   0             // 3 buffers: h ping, h pong, p2
#define OFF_C     27648         // [256][36] c state
#define OFF_PREV  36864         // [32][4]
#define OFF_WIH   36992         // [1024][4]
#define OFF_BG    41088         // [1024]
#define OFF_FB1   42112         // [256]
#define OFF_FB2   42368         // [256]
#define OFF_FC3   42624         // [256][4]  fc3T[k][d]
#define OFF_B3    43648         // [4]
#define SMEM_FLOATS 43652
#define SMEM_BYTES  (SMEM_FLOATS * 4)

// fc phase: 16 active warps; thread = units (jf, jf+32) x 8 rows (rf0..rf0+7)
__device__ __forceinline__ void fc_phase(const float* __restrict__ src,
                                         float* __restrict__ dst,
                                         const float4* __restrict__ wbase,
                                         const float* __restrict__ bsh,
                                         int jf, int rf0) {
    unsigned long long acc[2][4];
    {
        float b0 = bsh[jf], b1 = bsh[jf + 32];
        acc[0][0] = acc[0][1] = acc[0][2] = acc[0][3] = pk2(b0, b0);
        acc[1][0] = acc[1][1] = acc[1][2] = acc[1][3] = pk2(b1, b1);
    }
#pragma unroll 1
    for (int kc = 0; kc < KC; kc++) {
        // broadcast h loads: all lanes of warp read identical addresses
        const float* hb = src + kc * 144 + rf0;
        ulonglong2 h[4][2];
#pragma unroll
        for (int kk = 0; kk < 4; kk++) {
            h[kk][0] = *reinterpret_cast<const ulonglong2*>(hb + kk * 36);
            h[kk][1] = *reinterpret_cast<const ulonglong2*>(hb + kk * 36 + 4);
        }
        float4 w0 = wbase[kc * HID + jf];
        float4 w1 = wbase[kc * HID + jf + 32];
#pragma unroll
        for (int u = 0; u < 2; u++) {
            float4 wv = (u == 0) ? w0 : w1;
#pragma unroll
            for (int kk = 0; kk < 4; kk++) {
                float wk = (kk == 0) ? wv.x : (kk == 1) ? wv.y : (kk == 2) ? wv.z : wv.w;
                unsigned long long w2 = pk2(wk, wk);
                fma2(acc[u][0], w2, h[kk][0].x);
                fma2(acc[u][1], w2, h[kk][0].y);
                fma2(acc[u][2], w2, h[kk][1].x);
                fma2(acc[u][3], w2, h[kk][1].y);
            }
        }
    }
#pragma unroll
    for (int u = 0; u < 2; u++) {
        const int j = jf + u * 32;
        float v0, v1, v2, v3, v4, v5, v6, v7;
        unpk2(acc[u][0], v0, v1); unpk2(acc[u][1], v2, v3);
        unpk2(acc[u][2], v4, v5); unpk2(acc[u][3], v6, v7);
        *reinterpret_cast<float4*>(dst + j * 36 + rf0) =
            make_float4(fmaxf(v0, 0.f), fmaxf(v1, 0.f), fmaxf(v2, 0.f), fmaxf(v3, 0.f));
        *reinterpret_cast<float4*>(dst + j * 36 + rf0 + 4) =
            make_float4(fmaxf(v4, 0.f), fmaxf(v5, 0.f), fmaxf(v6, 0.f), fmaxf(v7, 0.f));
    }
}

__global__ void __launch_bounds__(1024, 1)
rnn_rollout_kernel(const float* __restrict__ inputs,
                   const float* __restrict__ W_ih,
                   const float* __restrict__ b_ih,
                   const float* __restrict__ b_hh,
                   const float* __restrict__ fc1_b,
                   const float* __restrict__ fc2_b,
                   const float* __restrict__ fc3_w,
                   const float* __restrict__ fc3_b,
                   float* __restrict__ out) {
    extern __shared__ float sm[];
    float* buf    = sm + OFF_BUF;
    float* csh    = sm + OFF_C;
    float* prevsh = sm + OFF_PREV;
    float* wihsh  = sm + OFF_WIH;
    float* bgsh   = sm + OFF_BG;
    float* fb1sh  = sm + OFF_FB1;
    float* fb2sh  = sm + OFF_FB2;
    float* fc3T   = sm + OFF_FC3;
    float* b3sh   = sm + OFF_B3;

    const int tid  = threadIdx.x;
    const int w    = tid >> 5;
    const int l    = tid & 31;
    // phase A / elementwise mapping: warp = 32 consecutive j2 x 1 rowgroup
    const int j2   = (w & 7) * 32 + l;   // 0..255
    const int rg   = w >> 3;             // 0..3
    const int r0   = rg * 8;
    // fc mapping (warps 0..15): thread = units (jf, jf+32) x rows rf0..rf0+7
    const int jf   = (w & 3) * 64 + l;
    const int rf0  = (w >> 2) * 8;
    const int row0 = blockIdx.x * MROWS;

    // ---- one-time init ----
    *reinterpret_cast<float4*>(wihsh + tid * 4) =
        *reinterpret_cast<const float4*>(W_ih + tid * 4);
    bgsh[tid] = b_ih[tid] + b_hh[tid];
    if (tid < HID) { fb1sh[tid] = fc1_b[tid]; fb2sh[tid] = fc2_b[tid]; }
    fc3T[tid] = fc3_w[(tid & 3) * HID + (tid >> 2)];
    if (tid < DIN) b3sh[tid] = fc3_b[tid];
    for (int i = tid; i < 3 * SBUF; i += 1024) buf[i] = 0.0f;
    for (int i = tid; i < SBUF; i += 1024) csh[i] = 0.0f;
    if (tid < MROWS * DIN)
        prevsh[tid] = inputs[((size_t)(row0 + (tid >> 2)) * T_STEPS) * DIN + (tid & 3)];
    __syncthreads();

    for (int t = 0; t < T_STEPS; t++) {
        const int par = t & 1;
        float* hin  = buf + par * SBUF;
        float* hout = buf + (par ^ 1) * SBUF;
        float* p1   = hin;                 // fc1 overwrites dead h_in
        float* p2   = buf + 2 * SBUF;

        // ---- phase A: gate GEMM. thread = j2 x 4 gates x 8 rows ----
        unsigned long long acc[4][4];
        {
#pragma unroll
            for (int g = 0; g < 4; g++) {
                float4 wg = *reinterpret_cast<const float4*>(wihsh + (g * 256 + j2) * 4);
                float b = bgsh[g * 256 + j2];
#pragma unroll
                for (int p = 0; p < 4; p++) {
                    float4 pa = *reinterpret_cast<const float4*>(prevsh + 4 * (r0 + 2 * p));
                    float4 pb = *reinterpret_cast<const float4*>(prevsh + 4 * (r0 + 2 * p + 1));
                    acc[g][p] = pk2(b + wg.x*pa.x + wg.y*pa.y + wg.z*pa.z + wg.w*pa.w,
                                    b + wg.x*pb.x + wg.y*pb.y + wg.z*pb.z + wg.w*pb.w);
                }
            }
        }
#pragma unroll 1
        for (int kc = 0; kc < KC; kc++) {
            // broadcast h: 8 rows x 4 k-values, identical across lanes
            const float* hb = hin + kc * 144 + r0;
            ulonglong2 h[4][2];
#pragma unroll
            for (int kk = 0; kk < 4; kk++) {
                h[kk][0] = *reinterpret_cast<const ulonglong2*>(hb + kk * 36);
                h[kk][1] = *reinterpret_cast<const ulonglong2*>(hb + kk * 36 + 4);
            }
            const float4* wk = g_whh + kc * G4 + j2;
#pragma unroll
            for (int g = 0; g < 4; g++) {
                float4 wv = wk[g * 256];           // lane-distinct, coalesced
#pragma unroll
                for (int kk = 0; kk < 4; kk++) {
                    float wkk = (kk == 0) ? wv.x : (kk == 1) ? wv.y : (kk == 2) ? wv.z : wv.w;
                    unsigned long long w2 = pk2(wkk, wkk);
                    fma2(acc[g][0], w2, h[kk][0].x);
                    fma2(acc[g][1], w2, h[kk][0].y);
                    fma2(acc[g][2], w2, h[kk][1].x);
                    fma2(acc[g][3], w2, h[kk][1].y);
                }
            }
        }
        // ---- fused LSTM elementwise: (j2, rows r0..r0+7) ----
        {
            float4 cv0 = *reinterpret_cast<const float4*>(csh + j2 * 36 + r0);
            float4 cv1 = *reinterpret_cast<const float4*>(csh + j2 * 36 + r0 + 4);
            float cc[8] = {cv0.x, cv0.y, cv0.z, cv0.w, cv1.x, cv1.y, cv1.z, cv1.w};
            float hh[8];
#pragma unroll
            for (int p = 0; p < 4; p++) {
                float i0, i1, f0, f1, g0, g1, o0, o1;
                unpk2(acc[0][p], i0, i1);
                unpk2(acc[1][p], f0, f1);
                unpk2(acc[2][p], g0, g1);
                unpk2(acc[3][p], o0, o1);
                float c0 = sigf(f0) * cc[2*p]   + sigf(i0) * tanhf_fast(g0);
                float c1 = sigf(f1) * cc[2*p+1] + sigf(i1) * tanhf_fast(g1);
                cc[2*p]   = c0;
                cc[2*p+1] = c1;
                hh[2*p]   = sigf(o0) * tanhf_fast(c0);
                hh[2*p+1] = sigf(o1) * tanhf_fast(c1);
            }
            *reinterpret_cast<float4*>(csh + j2 * 36 + r0)     = make_float4(cc[0], cc[1], cc[2], cc[3]);
            *reinterpret_cast<float4*>(csh + j2 * 36 + r0 + 4) = make_float4(cc[4], cc[5], cc[6], cc[7]);
            *reinterpret_cast<float4*>(hout + j2 * 36 + r0)     = make_float4(hh[0], hh[1], hh[2], hh[3]);
            *reinterpret_cast<float4*>(hout + j2 * 36 + r0 + 4) = make_float4(hh[4], hh[5], hh[6], hh[7]);
        }
        __syncthreads();

        // ---- fc1: hout -> p1 (warps 0..15) ----
        if (w < 16) fc_phase(hout, p1, g_fc1, fb1sh, jf, rf0);
        __syncthreads();

        // ---- fc2: p1 -> p2 (warps 0..15) ----
        if (w < 16) fc_phase(p1, p2, g_fc2, fb2sh, jf, rf0);
        __syncthreads();

        // ---- fc3 + residual: warp w = row w (32 warps) ----
        {
            const int row = w;
            const int d   = l & 3;
            const int s   = l >> 2;
            const float* pp = p2 + row;
            float a0 = 0.f;
#pragma unroll 8
            for (int i = 0; i < 32; i++) {
                const int k = i * 8 + s;
                a0 = fmaf(pp[k * 36], fc3T[k * 4 + d], a0);
            }
            a0 += __shfl_xor_sync(0xffffffffu, a0, 4);
            a0 += __shfl_xor_sync(0xffffffffu, a0, 8);
            a0 += __shfl_xor_sync(0xffffffffu, a0, 16);
            if (s == 0) {
                float r = a0 + b3sh[d] + prevsh[row * 4 + d];
                out[((size_t)(row0 + row) * T_STEPS + t) * DIN + d] = r;
                prevsh[row * 4 + d] = r;
            }
        }
        __syncthreads();
    }
}

extern "C" void kernel_launch(void* const* d_in, const int* in_sizes, int n_in,
                              void* d_out, int out_size) {
    const float* inputs = (const float*)d_in[0];
    const float* W_ih   = (const float*)d_in[1];
    const float* W_hh   = (const float*)d_in[2];
    const float* b_ih   = (const float*)d_in[3];
    const float* b_hh   = (const float*)d_in[4];
    const float* fc1_w  = (const float*)d_in[5];
    const float* fc1_b  = (const float*)d_in[6];
    const float* fc2_w  = (const float*)d_in[7];
    const float* fc2_b  = (const float*)d_in[8];
    const float* fc3_w  = (const float*)d_in[9];
    const float* fc3_b  = (const float*)d_in[10];
    float* out = (float*)d_out;

    pack_kernel<<<64, 1024>>>(W_hh, fc1_w, fc2_w);

    cudaFuncSetAttribute(rnn_rollout_kernel,
                         cudaFuncAttributeMaxDynamicSharedMemorySize, SMEM_BYTES);
    rnn_rollout_kernel<<<NCTA, 1024, SMEM_BYTES>>>(
        inputs, W_ih, b_ih, b_hh, fc1_b, fc2_b, fc3_w, fc3_b, out);
}

// round 8
// speedup vs baseline: 1.0608x; 1.0009x over previous
#include <cuda_runtime.h>

// ---------------------------------------------------------------------------
// GraphRNNDecoder rollout. N=4096 rows, T=128 steps, D=4, H=256.
// 128 persistent CTAs x 1024 threads, 32 rows per CTA.
// R6: lane = output unit (coalesced weight LDG, 512B/instr), h via
// FULL-BROADCAST LDS (all 32 lanes same address ~= 1 wavefront).
// Phase A: thread = 1 j2 x 4 gates x 8 rows -> 26 wf per 32 FMA-cyc (FMA-bound).
// fc1/fc2: thread = 2 units x 8 rows on 16 warps.
// ---------------------------------------------------------------------------

#define T_STEPS 128
#define DIN     4
#define HID     256
#define G4      1024
#define MROWS   32
#define NCTA    128
#define KC      64

// k-chunk packed weights [kc][unit] -> float4 of W[unit][4kc..4kc+3]
__device__ float4 g_whh[KC * G4];   // 1 MB
__device__ float4 g_fc1[KC * HID];  // 256 KB
__device__ float4 g_fc2[KC * HID];  // 256 KB

__global__ void pack_kernel(const float* __restrict__ W_hh,
                            const float* __restrict__ fc1_w,
                            const float* __restrict__ fc2_w) {
    int i = blockIdx.x * blockDim.x + threadIdx.x;
    if (i < KC * G4) {
        int kc = i >> 10, j = i & 1023;
        g_whh[i] = *reinterpret_cast<const float4*>(W_hh + j * HID + kc * 4);
    }
    if (i < KC * HID) {
        int kc = i >> 8, j = i & 255;
        g_fc1[i] = *reinterpret_cast<const float4*>(fc1_w + j * HID + kc * 4);
        g_fc2[i] = *reinterpret_cast<const float4*>(fc2_w + j * HID + kc * 4);
    }
}

// ---- packed f32x2 helpers --------------------------------------------------
__device__ __forceinline__ unsigned long long pk2(float lo, float hi) {
    unsigned long long r;
    asm("mov.b64 %0, {%1, %2};" : "=l"(r) : "f"(lo), "f"(hi));
    return r;
}
__device__ __forceinline__ void fma2(unsigned long long& d,
                                     unsigned long long a,
                                     unsigned long long b) {
    asm("fma.rn.f32x2 %0, %1, %2, %0;" : "+l"(d) : "l"(a), "l"(b));
}
__device__ __forceinline__ void unpk2(unsigned long long v, float& lo, float& hi) {
    asm("mov.b64 {%0, %1}, %2;" : "=f"(lo), "=f"(hi) : "l"(v));
}
__device__ __forceinline__ float sigf(float x) {
    return __fdividef(1.0f, 1.0f + __expf(-x));
}
__device__ __forceinline__ float tanhf_fast(float x) {
    float e = __expf(2.0f * x);
    return 1.0f - __fdividef(2.0f, e + 1.0f);
}

// ---- shared layout (float offsets) -----------------------------------------
#define SBUF      9216          // one [256][36] activation buffer
#define OFF_BUF   0             // 3 buffers: h ping, h pong, p2
#define OFF_C     27648         // [256][36] c state
#define OFF_PREV  36864         // [32][4]
#define OFF_WIH   36992         // [1024][4]
#define OFF_BG    41088         // [1024]
#define OFF_FB1   42112         // [256]
#define OFF_FB2   42368         // [256]
#define OFF_FC3   42624         // [256][4]  fc3T[k][d]
#define OFF_B3    43648         // [4]
#define SMEM_FLOATS 43652
#define SMEM_BYTES  (SMEM_FLOATS * 4)

// fc phase: 16 active warps; thread = units (jf, jf+32) x 8 rows (rf0..rf0+7)
__device__ __forceinline__ void fc_phase(const float* __restrict__ src,
                                         float* __restrict__ dst,
                                         const float4* __restrict__ wbase,
                                         const float* __restrict__ bsh,
                                         int jf, int rf0) {
    unsigned long long acc[2][4];
    {
        float b0 = bsh[jf], b1 = bsh[jf + 32];
        acc[0][0] = acc[0][1] = acc[0][2] = acc[0][3] = pk2(b0, b0);
        acc[1][0] = acc[1][1] = acc[1][2] = acc[1][3] = pk2(b1, b1);
    }
#pragma unroll 1
    for (int kc = 0; kc < KC; kc++) {
        // broadcast h loads: all lanes of warp read identical addresses
        const float* hb = src + kc * 144 + rf0;
        ulonglong2 h[4][2];
#pragma unroll
        for (int kk = 0; kk < 4; kk++) {
            h[kk][0] = *reinterpret_cast<const ulonglong2*>(hb + kk * 36);
            h[kk][1] = *reinterpret_cast<const ulonglong2*>(hb + kk * 36 + 4);
        }
        float4 w0 = wbase[kc * HID + jf];
        float4 w1 = wbase[kc * HID + jf + 32];
#pragma unroll
        for (int u = 0; u < 2; u++) {
            float4 wv = (u == 0) ? w0 : w1;
#pragma unroll
            for (int kk = 0; kk < 4; kk++) {
                float wk = (kk == 0) ? wv.x : (kk == 1) ? wv.y : (kk == 2) ? wv.z : wv.w;
                unsigned long long w2 = pk2(wk, wk);
                fma2(acc[u][0], w2, h[kk][0].x);
                fma2(acc[u][1], w2, h[kk][0].y);
                fma2(acc[u][2], w2, h[kk][1].x);
                fma2(acc[u][3], w2, h[kk][1].y);
            }
        }
    }
#pragma unroll
    for (int u = 0; u < 2; u++) {
        const int j = jf + u * 32;
        float v0, v1, v2, v3, v4, v5, v6, v7;
        unpk2(acc[u][0], v0, v1); unpk2(acc[u][1], v2, v3);
        unpk2(acc[u][2], v4, v5); unpk2(acc[u][3], v6, v7);
        *reinterpret_cast<float4*>(dst + j * 36 + rf0) =
            make_float4(fmaxf(v0, 0.f), fmaxf(v1, 0.f), fmaxf(v2, 0.f), fmaxf(v3, 0.f));
        *reinterpret_cast<float4*>(dst + j * 36 + rf0 + 4) =
            make_float4(fmaxf(v4, 0.f), fmaxf(v5, 0.f), fmaxf(v6, 0.f), fmaxf(v7, 0.f));
    }
}

__global__ void __launch_bounds__(1024, 1)
rnn_rollout_kernel(const float* __restrict__ inputs,
                   const float* __restrict__ W_ih,
                   const float* __restrict__ b_ih,
                   const float* __restrict__ b_hh,
                   const float* __restrict__ fc1_b,
                   const float* __restrict__ fc2_b,
                   const float* __restrict__ fc3_w,
                   const float* __restrict__ fc3_b,
                   float* __restrict__ out) {
    extern __shared__ float sm[];
    float* buf    = sm + OFF_BUF;
    float* csh    = sm + OFF_C;
    float* prevsh = sm + OFF_PREV;
    float* wihsh  = sm + OFF_WIH;
    float* bgsh   = sm + OFF_BG;
    float* fb1sh  = sm + OFF_FB1;
    float* fb2sh  = sm + OFF_FB2;
    float* fc3T   = sm + OFF_FC3;
    float* b3sh   = sm + OFF_B3;

    const int tid  = threadIdx.x;
    const int w    = tid >> 5;
    const int l    = tid & 31;
    // phase A / elementwise mapping: warp = 32 consecutive j2 x 1 rowgroup
    const int j2   = (w & 7) * 32 + l;   // 0..255
    const int rg   = w >> 3;             // 0..3
    const int r0   = rg * 8;
    // fc mapping (warps 0..15): thread = units (jf, jf+32) x rows rf0..rf0+7
    const int jf   = (w & 3) * 64 + l;
    const int rf0  = (w >> 2) * 8;
    const int row0 = blockIdx.x * MROWS;

    // ---- one-time init ----
    *reinterpret_cast<float4*>(wihsh + tid * 4) =
        *reinterpret_cast<const float4*>(W_ih + tid * 4);
    bgsh[tid] = b_ih[tid] + b_hh[tid];
    if (tid < HID) { fb1sh[tid] = fc1_b[tid]; fb2sh[tid] = fc2_b[tid]; }
    fc3T[tid] = fc3_w[(tid & 3) * HID + (tid >> 2)];
    if (tid < DIN) b3sh[tid] = fc3_b[tid];
    for (int i = tid; i < 3 * SBUF; i += 1024) buf[i] = 0.0f;
    for (int i = tid; i < SBUF; i += 1024) csh[i] = 0.0f;
    if (tid < MROWS * DIN)
        prevsh[tid] = inputs[((size_t)(row0 + (tid >> 2)) * T_STEPS) * DIN + (tid & 3)];
    __syncthreads();

    for (int t = 0; t < T_STEPS; t++) {
        const int par = t & 1;
        float* hin  = buf + par * SBUF;
        float* hout = buf + (par ^ 1) * SBUF;
        float* p1   = hin;                 // fc1 overwrites dead h_in
        float* p2   = buf + 2 * SBUF;

        // ---- phase A: gate GEMM. thread = j2 x 4 gates x 8 rows ----
        unsigned long long acc[4][4];
        {
#pragma unroll
            for (int g = 0; g < 4; g++) {
                float4 wg = *reinterpret_cast<const float4*>(wihsh + (g * 256 + j2) * 4);
                float b = bgsh[g * 256 + j2];
#pragma unroll
                for (int p = 0; p < 4; p++) {
                    float4 pa = *reinterpret_cast<const float4*>(prevsh + 4 * (r0 + 2 * p));
                    float4 pb = *reinterpret_cast<const float4*>(prevsh + 4 * (r0 + 2 * p + 1));
                    acc[g][p] = pk2(b + wg.x*pa.x + wg.y*pa.y + wg.z*pa.z + wg.w*pa.w,
                                    b + wg.x*pb.x + wg.y*pb.y + wg.z*pb.z + wg.w*pb.w);
                }
            }
        }
#pragma unroll 1
        for (int kc = 0; kc < KC; kc++) {
            // broadcast h: 8 rows x 4 k-values, identical across lanes
            const float* hb = hin + kc * 144 + r0;
            ulonglong2 h[4][2];
#pragma unroll
            for (int kk = 0; kk < 4; kk++) {
                h[kk][0] = *reinterpret_cast<const ulonglong2*>(hb + kk * 36);
                h[kk][1] = *reinterpret_cast<const ulonglong2*>(hb + kk * 36 + 4);
            }
            const float4* wk = g_whh + kc * G4 + j2;
#pragma unroll
            for (int g = 0; g < 4; g++) {
                float4 wv = wk[g * 256];           // lane-distinct, coalesced
#pragma unroll
                for (int kk = 0; kk < 4; kk++) {
                    float wkk = (kk == 0) ? wv.x : (kk == 1) ? wv.y : (kk == 2) ? wv.z : wv.w;
                    unsigned long long w2 = pk2(wkk, wkk);
                    fma2(acc[g][0], w2, h[kk][0].x);
                    fma2(acc[g][1], w2, h[kk][0].y);
                    fma2(acc[g][2], w2, h[kk][1].x);
                    fma2(acc[g][3], w2, h[kk][1].y);
                }
            }
        }
        // ---- fused LSTM elementwise: (j2, rows r0..r0+7) ----
        {
            float4 cv0 = *reinterpret_cast<const float4*>(csh + j2 * 36 + r0);
            float4 cv1 = *reinterpret_cast<const float4*>(csh + j2 * 36 + r0 + 4);
            float cc[8] = {cv0.x, cv0.y, cv0.z, cv0.w, cv1.x, cv1.y, cv1.z, cv1.w};
            float hh[8];
#pragma unroll
            for (int p = 0; p < 4; p++) {
                float i0, i1, f0, f1, g0, g1, o0, o1;
                unpk2(acc[0][p], i0, i1);
                unpk2(acc[1][p], f0, f1);
                unpk2(acc[2][p], g0, g1);
                unpk2(acc[3][p], o0, o1);
                float c0 = sigf(f0) * cc[2*p]   + sigf(i0) * tanhf_fast(g0);
                float c1 = sigf(f1) * cc[2*p+1] + sigf(i1) * tanhf_fast(g1);
                cc[2*p]   = c0;
                cc[2*p+1] = c1;
                hh[2*p]   = sigf(o0) * tanhf_fast(c0);
                hh[2*p+1] = sigf(o1) * tanhf_fast(c1);
            }
            *reinterpret_cast<float4*>(csh + j2 * 36 + r0)     = make_float4(cc[0], cc[1], cc[2], cc[3]);
            *reinterpret_cast<float4*>(csh + j2 * 36 + r0 + 4) = make_float4(cc[4], cc[5], cc[6], cc[7]);
            *reinterpret_cast<float4*>(hout + j2 * 36 + r0)     = make_float4(hh[0], hh[1], hh[2], hh[3]);
            *reinterpret_cast<float4*>(hout + j2 * 36 + r0 + 4) = make_float4(hh[4], hh[5], hh[6], hh[7]);
        }
        __syncthreads();

        // ---- fc1: hout -> p1 (warps 0..15) ----
        if (w < 16) fc_phase(hout, p1, g_fc1, fb1sh, jf, rf0);
        __syncthreads();

        // ---- fc2: p1 -> p2 (warps 0..15) ----
        if (w < 16) fc_phase(p1, p2, g_fc2, fb2sh, jf, rf0);
        __syncthreads();

        // ---- fc3 + residual: warp w = row w (32 warps) ----
        {
            const int row = w;
            const int d   = l & 3;
            const int s   = l >> 2;
            const float* pp = p2 + row;
            float a0 = 0.f;
#pragma unroll 8
            for (int i = 0; i < 32; i++) {
                const int k = i * 8 + s;
                a0 = fmaf(pp[k * 36], fc3T[k * 4 + d], a0);
            }
            a0 += __shfl_xor_sync(0xffffffffu, a0, 4);
            a0 += __shfl_xor_sync(0xffffffffu, a0, 8);
            a0 += __shfl_xor_sync(0xffffffffu, a0, 16);
            if (s == 0) {
                float r = a0 + b3sh[d] + prevsh[row * 4 + d];
                out[((size_t)(row0 + row) * T_STEPS + t) * DIN + d] = r;
                prevsh[row * 4 + d] = r;
            }
        }
        __syncthreads();
    }
}

extern "C" void kernel_launch(void* const* d_in, const int* in_sizes, int n_in,
                              void* d_out, int out_size) {
    const float* inputs = (const float*)d_in[0];
    const float* W_ih   = (const float*)d_in[1];
    const float* W_hh   = (const float*)d_in[2];
    const float* b_ih   = (const float*)d_in[3];
    const float* b_hh   = (const float*)d_in[4];
    const float* fc1_w  = (const float*)d_in[5];
    const float* fc1_b  = (const float*)d_in[6];
    const float* fc2_w  = (const float*)d_in[7];
    const float* fc2_b  = (const float*)d_in[8];
    const float* fc3_w  = (const float*)d_in[9];
    const float* fc3_b  = (const float*)d_in[10];
    float* out = (float*)d_out;

    pack_kernel<<<64, 1024>>>(W_hh, fc1_w, fc2_w);

    cudaFuncSetAttribute(rnn_rollout_kernel,
                         cudaFuncAttributeMaxDynamicSharedMemorySize, SMEM_BYTES);
    rnn_rollout_kernel<<<NCTA, 1024, SMEM_BYTES>>>(
        inputs, W_ih, b_ih, b_hh, fc1_b, fc2_b, fc3_w, fc3_b, out);
}